// round 6
// baseline (speedup 1.0000x reference)
#include <cuda_runtime.h>
#include <cuda_fp16.h>
#include <math.h>

#define HH   192
#define WW   192
#define CIN  64
#define SHC  8
#define NB   8
#define NPIX (HH*WW)

typedef unsigned long long ull;

// scratch for h = gelu(conv1(x)), PIXEL-MAJOR: [b][pix][8 sh-channels] (9.4 MB)
__device__ float g_h[(size_t)NB * NPIX * SHC];

__device__ __forceinline__ void cp_async4(void* dst, const void* src) {
    unsigned s = (unsigned)__cvta_generic_to_shared(dst);
    asm volatile("cp.async.ca.shared.global [%0], [%1], 4;\n" :: "r"(s), "l"(src));
}
__device__ __forceinline__ float fsqrt_approx(float v) {
    float r; asm("sqrt.approx.f32 %0, %1;" : "=f"(r) : "f"(v)); return r;
}
// ---- f32x2 packed helpers ----
__device__ __forceinline__ ull ffma2(ull a, ull b, ull c) {
    ull r; asm("fma.rn.f32x2 %0, %1, %2, %3;" : "=l"(r) : "l"(a), "l"(b), "l"(c)); return r;
}
__device__ __forceinline__ ull dup2(float v) {
    ull r; asm("mov.b64 %0, {%1, %1};" : "=l"(r) : "f"(v)); return r;
}
__device__ __forceinline__ ull pack2(float lo, float hi) {
    ull r; asm("mov.b64 %0, {%1, %2};" : "=l"(r) : "f"(lo), "f"(hi)); return r;
}
__device__ __forceinline__ void unpack2(ull v, float& lo, float& hi) {
    asm("mov.b64 {%0, %1}, %2;" : "=f"(lo), "=f"(hi) : "l"(v));
}

// ---------------------------------------------------------------------------
// Kernel 1: 3x3 SAME conv (64 -> 8) + exact GELU  (at scalar issue floor).
// ---------------------------------------------------------------------------
__global__ void __launch_bounds__(256, 1)
conv1_gelu_kernel(const float* __restrict__ x, const float* __restrict__ w1)
{
    __shared__ float wsm[CIN * 9 * SHC];
    __shared__ float dsm[2][34 * 68];

    const int tid   = threadIdx.x;
    const int b     = blockIdx.z;
    const int tileX = blockIdx.x * 64;
    const int tileY = blockIdx.y * 32;

    for (int i = tid; i < CIN * 9 * SHC; i += 256) {
        int oc  = i & 7;
        int tap = (i >> 3) % 9;
        int ic  = i / 72;
        wsm[i] = w1[(oc * CIN + ic) * 9 + tap];
    }

    const float* xb = x + (size_t)b * CIN * NPIX;

    auto load_tile = [&](int ic, int buf) {
        const float* src = xb + (size_t)ic * NPIX;
        for (int i = tid; i < 34 * 66; i += 256) {
            int r    = i / 66;
            int ccol = i - r * 66;
            int gy   = tileY - 1 + r;
            int gx   = tileX - 1 + ccol;
            float* dp = &dsm[buf][r * 68 + ccol];
            if ((unsigned)gy < (unsigned)HH && (unsigned)gx < (unsigned)WW)
                cp_async4(dp, src + gy * WW + gx);
            else
                *dp = 0.f;
        }
    };

    load_tile(0, 0);
    asm volatile("cp.async.commit_group;\n");

    const int tx = (tid & 7) * 8;
    const int ty = tid >> 3;

    ull acc2[4][8];
    #pragma unroll
    for (int q = 0; q < 4; q++)
        #pragma unroll
        for (int p = 0; p < 8; p++) acc2[q][p] = 0ull;

    for (int ic = 0; ic < CIN; ic++) {
        __syncthreads();
        if (ic + 1 < CIN) {
            load_tile(ic + 1, (ic + 1) & 1);
            asm volatile("cp.async.commit_group;\n");
            asm volatile("cp.async.wait_group 1;\n");
        } else {
            asm volatile("cp.async.wait_group 0;\n");
        }
        __syncthreads();

        const float* dd = &dsm[ic & 1][ty * 68 + tx];
        float rw[3][10];
        #pragma unroll
        for (int q = 0; q < 10; q++) {
            rw[0][q] = dd[q];
            rw[1][q] = dd[68 + q];
            rw[2][q] = dd[136 + q];
        }
        const float* wp = &wsm[ic * 72];
        #pragma unroll
        for (int t = 0; t < 9; t++) {
            const int ky = t / 3, kx = t % 3;
            const ull* wq = reinterpret_cast<const ull*>(wp + t * 8);
            ull w0 = wq[0], w1q = wq[1], w2q = wq[2], w3q = wq[3];
            #pragma unroll
            for (int p = 0; p < 8; p++) {
                ull d = dup2(rw[ky][p + kx]);
                acc2[0][p] = ffma2(d, w0,  acc2[0][p]);
                acc2[1][p] = ffma2(d, w1q, acc2[1][p]);
                acc2[2][p] = ffma2(d, w2q, acc2[2][p]);
                acc2[3][p] = ffma2(d, w3q, acc2[3][p]);
            }
        }
    }

    const int gy  = tileY + ty;
    const int gx0 = tileX + tx;
    const float inv_sqrt2 = 0.70710678118654752f;
    float* hbase = g_h + ((size_t)b * NPIX + (size_t)gy * WW + gx0) * SHC;
    #pragma unroll
    for (int p = 0; p < 8; p++) {
        float v[8];
        unpack2(acc2[0][p], v[0], v[1]);
        unpack2(acc2[1][p], v[2], v[3]);
        unpack2(acc2[2][p], v[4], v[5]);
        unpack2(acc2[3][p], v[6], v[7]);
        float4 o0, o1;
        float u;
        u = v[0]; o0.x = 0.5f * u * (1.f + erff(u * inv_sqrt2));
        u = v[1]; o0.y = 0.5f * u * (1.f + erff(u * inv_sqrt2));
        u = v[2]; o0.z = 0.5f * u * (1.f + erff(u * inv_sqrt2));
        u = v[3]; o0.w = 0.5f * u * (1.f + erff(u * inv_sqrt2));
        u = v[4]; o1.x = 0.5f * u * (1.f + erff(u * inv_sqrt2));
        u = v[5]; o1.y = 0.5f * u * (1.f + erff(u * inv_sqrt2));
        u = v[6]; o1.z = 0.5f * u * (1.f + erff(u * inv_sqrt2));
        u = v[7]; o1.w = 0.5f * u * (1.f + erff(u * inv_sqrt2));
        float4* hp = reinterpret_cast<float4*>(hbase + (size_t)p * SHC);
        hp[0] = o0;
        hp[1] = o1;
    }
}

// ---------------------------------------------------------------------------
// Kernel 2: dual-copy half2 image in smem. Copy A = half(img); copy B =
// half(img) shifted one pixel. Any (img[o], img[o+1]) pair = ONE LDS.32.
// 8 tap-LDS per pixel instead of 16. Lerps in fp32. xv via coalesced LDG.
// ---------------------------------------------------------------------------
#define PAD 200
#define W32 ((NPIX + PAD) / 2)      // 18532 words per copy

__device__ __forceinline__ float bilin_tap(const unsigned* __restrict__ A,
                                           const unsigned* __restrict__ Bc,
                                           int o, float wx, float wy)
{
    const unsigned* base = (o & 1) ? Bc : A;
    int w = o >> 1;
    unsigned r0 = base[w];
    unsigned r1 = base[w + 96];     // +192 halves = next row, same parity
    float2 t0 = __half22float2(*reinterpret_cast<__half2*>(&r0));
    float2 t1 = __half22float2(*reinterpret_cast<__half2*>(&r1));
    float top = fmaf(t0.y - t0.x, wx, t0.x);
    float bot = fmaf(t1.y - t1.x, wx, t1.x);
    return fmaf(bot - top, wy, top);
}

__global__ void __launch_bounds__(576, 1)
fuse_kernel(const float* __restrict__ x, const float* __restrict__ w2,
            const float* __restrict__ b2, const float* __restrict__ lsc,
            float* __restrict__ out)
{
    extern __shared__ unsigned smem_u[];     // A[W32+1], B[W32]
    unsigned* A  = smem_u;
    unsigned* Bc = smem_u + W32 + 1;

    const int tid  = threadIdx.x;
    const int bc   = blockIdx.x >> 1;
    const int half = blockIdx.x & 1;
    const int c    = bc & 63;

    const float* xg = x + (size_t)bc * NPIX;

    // ---- stage pass 1: fp32 -> half2 copy A ----
    const float4* src = reinterpret_cast<const float4*>(xg);
    #pragma unroll 4
    for (int i = tid; i < NPIX / 4; i += 576) {
        float4 f = src[i];
        __half2 h01 = __floats2half2_rn(f.x, f.y);
        __half2 h23 = __floats2half2_rn(f.z, f.w);
        uint2 u;
        u.x = *reinterpret_cast<unsigned*>(&h01);
        u.y = *reinterpret_cast<unsigned*>(&h23);
        *reinterpret_cast<uint2*>(A + 2 * i) = u;
    }
    for (int i = NPIX / 2 + tid; i < W32 + 1; i += 576) A[i] = 0;  // zero pad
    __syncthreads();

    // ---- stage pass 2: shifted copy B (B halves[j] = img[j+1]) ----
    for (int k = tid; k < W32; k += 576)
        Bc[k] = __funnelshift_r(A[k], A[k + 1], 16);

    // pre-scaled packed weights (pixel-space folding from R5)
    const float PXS = 9.55f;                 // 0.1 * 95.5
    ull w01[8], w23[8];
    #pragma unroll
    for (int s = 0; s < 8; s++) {
        w01[s] = pack2(__ldg(&w2[(4 * c + 0) * 8 + s]),
                       __ldg(&w2[(4 * c + 1) * 8 + s]) * PXS);
        w23[s] = pack2(__ldg(&w2[(4 * c + 2) * 8 + s]) * PXS,
                       __ldg(&w2[(4 * c + 3) * 8 + s]));
    }
    const ull bias01 = pack2(__ldg(&b2[4 * c + 0]), __ldg(&b2[4 * c + 1]) * PXS);
    const ull bias23 = pack2(__ldg(&b2[4 * c + 2]) * PXS, __ldg(&b2[4 * c + 3]));

    const float esc   = expf(__ldg(lsc));
    const float esc4  = 0.25f * esc;
    const float esc01 = 0.1f  * esc;
    const float* hb = g_h + (size_t)(bc >> 6) * NPIX * SHC;
    float* ob = out + (size_t)bc * NPIX;

    const float step = 2.0f / 191.0f;

    const int rphase = tid / 192;            // 0..2
    const int xi     = tid - rphase * 192;   // 0..191
    const float gxpix = (fmaf((float)xi, step, -1.0f) + 1.0f) * 95.5f;
    const int y0 = half * 96 + rphase;

    // prefetch first iteration's h before the staging barrier completes
    const int idxA0 = y0 * WW + xi;
    float4 ph0A = reinterpret_cast<const float4*>(hb + (size_t)idxA0 * SHC)[0];
    float4 ph1A = reinterpret_cast<const float4*>(hb + (size_t)idxA0 * SHC)[1];
    float4 ph0B = reinterpret_cast<const float4*>(hb + (size_t)(idxA0 + 48 * WW) * SHC)[0];
    float4 ph1B = reinterpret_cast<const float4*>(hb + (size_t)(idxA0 + 48 * WW) * SHC)[1];

    __syncthreads();

    #pragma unroll 1
    for (int k = 0; k < 16; k++) {
        const int yiA  = y0 + 3 * k;
        const int idxA = yiA * WW + xi;

        int   idx[2]   = { idxA, idxA + 48 * WW };
        float gypix[2] = { (fmaf((float)yiA,        step, -1.0f) + 1.0f) * 95.5f,
                           (fmaf((float)(yiA + 48), step, -1.0f) + 1.0f) * 95.5f };

        float4 h0[2], h1[2];
        h0[0] = ph0A; h1[0] = ph1A;
        h0[1] = ph0B; h1[1] = ph1B;
        if (k < 15) {
            const int nIdx = idxA + 3 * WW;
            ph0A = reinterpret_cast<const float4*>(hb + (size_t)nIdx * SHC)[0];
            ph1A = reinterpret_cast<const float4*>(hb + (size_t)nIdx * SHC)[1];
            ph0B = reinterpret_cast<const float4*>(hb + (size_t)(nIdx + 48 * WW) * SHC)[0];
            ph1B = reinterpret_cast<const float4*>(hb + (size_t)(nIdx + 48 * WW) * SHC)[1];
        }

        // exact fp32 x values for the 0.1*c*x term (coalesced L1/L2 hits)
        float xv[2] = { __ldg(xg + idx[0]), __ldg(xg + idx[1]) };

        float s95[2], dxp[2], dyp[2], cvv[2];
        #pragma unroll
        for (int j = 0; j < 2; j++) {
            ull a01 = bias01, a23 = bias23;
            ull d;
            d = dup2(h0[j].x); a01 = ffma2(d, w01[0], a01); a23 = ffma2(d, w23[0], a23);
            d = dup2(h0[j].y); a01 = ffma2(d, w01[1], a01); a23 = ffma2(d, w23[1], a23);
            d = dup2(h0[j].z); a01 = ffma2(d, w01[2], a01); a23 = ffma2(d, w23[2], a23);
            d = dup2(h0[j].w); a01 = ffma2(d, w01[3], a01); a23 = ffma2(d, w23[3], a23);
            d = dup2(h1[j].x); a01 = ffma2(d, w01[4], a01); a23 = ffma2(d, w23[4], a23);
            d = dup2(h1[j].y); a01 = ffma2(d, w01[5], a01); a23 = ffma2(d, w23[5], a23);
            d = dup2(h1[j].z); a01 = ffma2(d, w01[6], a01); a23 = ffma2(d, w23[6], a23);
            d = dup2(h1[j].w); a01 = ffma2(d, w01[7], a01); a23 = ffma2(d, w23[7], a23);
            float a, bxp, byp, cv;
            unpack2(a01, a, bxp);
            unpack2(a23, byp, cv);

            float t  = __expf(-fabsf(a));
            float sp = fmaxf(a, 0.f) + __logf(1.0f + t);
            s95[j] = fsqrt_approx(fmaf(sp, 912.025f, 9.12025e-5f));  // 95.5*sqrt(sp*.1+1e-8)
            dxp[j] = bxp;
            dyp[j] = byp;
            cvv[j] = fminf(fmaxf(cv, -5.f), 5.f);
        }

        #pragma unroll
        for (int j = 0; j < 2; j++) {
            float px3  = gxpix    + dxp[j];
            float px1  = px3      + s95[j];
            float px2  = px3      - s95[j];
            float py12 = gypix[j] + dyp[j];
            float py3  = py12     + s95[j];
            float py4  = py12     - s95[j];

            // shared row for u1,u2
            float pyc = fminf(fmaxf(py12, 0.f), 191.f);
            float y0f = floorf(pyc);
            float wy  = pyc - y0f;

            float pxc1 = fminf(fmaxf(px1, 0.f), 191.f);
            float x0f1 = floorf(pxc1);
            float wx1  = pxc1 - x0f1;
            int   o1   = (int)fmaf(y0f, 192.f, x0f1);
            float u1 = bilin_tap(A, Bc, o1, wx1, wy);

            float pxc2 = fminf(fmaxf(px2, 0.f), 191.f);
            float x0f2 = floorf(pxc2);
            float wx2  = pxc2 - x0f2;
            int   o2   = (int)fmaf(y0f, 192.f, x0f2);
            float u2 = bilin_tap(A, Bc, o2, wx2, wy);

            // shared column for u3,u4
            float pxc3 = fminf(fmaxf(px3, 0.f), 191.f);
            float x0f3 = floorf(pxc3);
            float wx3  = pxc3 - x0f3;

            float pyc3 = fminf(fmaxf(py3, 0.f), 191.f);
            float y0f3 = floorf(pyc3);
            float wy3  = pyc3 - y0f3;
            int   o3   = (int)fmaf(y0f3, 192.f, x0f3);
            float u3 = bilin_tap(A, Bc, o3, wx3, wy3);

            float pyc4 = fminf(fmaxf(py4, 0.f), 191.f);
            float y0f4 = floorf(pyc4);
            float wy4  = pyc4 - y0f4;
            int   o4   = (int)fmaf(y0f4, 192.f, x0f3);
            float u4 = bilin_tap(A, Bc, o4, wx3, wy4);

            float usum = (u1 + u2) + (u3 + u4);
            ob[idx[j]] = fmaf(esc4, usum, esc01 * cvv[j] * xv[j]);
        }
    }
}

// ---------------------------------------------------------------------------
extern "C" void kernel_launch(void* const* d_in, const int* in_sizes, int n_in,
                              void* d_out, int out_size)
{
    const float *x = nullptr, *w1 = nullptr, *w2 = nullptr, *b2 = nullptr, *ls = nullptr;
    for (int i = 0; i < n_in; i++) {
        switch (in_sizes[i]) {
            case NB * CIN * NPIX: x  = (const float*)d_in[i]; break;
            case SHC * CIN * 9:   w1 = (const float*)d_in[i]; break;
            case 4 * CIN * SHC:   w2 = (const float*)d_in[i]; break;
            case 4 * CIN:         b2 = (const float*)d_in[i]; break;
            case 1:               ls = (const float*)d_in[i]; break;
            default: break;
        }
    }

    dim3 g1(3, 6, NB);
    conv1_gelu_kernel<<<g1, 256>>>(x, w1);

    const int smem = (2 * W32 + 1) * (int)sizeof(unsigned);   // 148260 B
    cudaFuncSetAttribute(fuse_kernel, cudaFuncAttributeMaxDynamicSharedMemorySize, smem);
    fuse_kernel<<<NB * CIN * 2, 576, smem>>>(x, w2, b2, ls, (float*)d_out);
}

// round 7
// speedup vs baseline: 1.0785x; 1.0785x over previous
#include <cuda_runtime.h>
#include <math.h>

#define HH   192
#define WW   192
#define CIN  64
#define SHC  8
#define NB   8
#define NPIX (HH*WW)

typedef unsigned long long ull;

// scratch for h = gelu(conv1(x)), PIXEL-MAJOR: [b][pix][8 sh-channels] (9.4 MB)
__device__ float g_h[(size_t)NB * NPIX * SHC];

__device__ __forceinline__ void cp_async4(void* dst, const void* src) {
    unsigned s = (unsigned)__cvta_generic_to_shared(dst);
    asm volatile("cp.async.ca.shared.global [%0], [%1], 4;\n" :: "r"(s), "l"(src));
}
__device__ __forceinline__ float fsqrt_approx(float v) {
    float r; asm("sqrt.approx.f32 %0, %1;" : "=f"(r) : "f"(v)); return r;
}
// ---- f32x2 packed helpers ----
__device__ __forceinline__ ull ffma2(ull a, ull b, ull c) {
    ull r; asm("fma.rn.f32x2 %0, %1, %2, %3;" : "=l"(r) : "l"(a), "l"(b), "l"(c)); return r;
}
__device__ __forceinline__ ull dup2(float v) {
    ull r; asm("mov.b64 %0, {%1, %1};" : "=l"(r) : "f"(v)); return r;
}
__device__ __forceinline__ ull pack2(float lo, float hi) {
    ull r; asm("mov.b64 %0, {%1, %2};" : "=l"(r) : "f"(lo), "f"(hi)); return r;
}
__device__ __forceinline__ void unpack2(ull v, float& lo, float& hi) {
    asm("mov.b64 {%0, %1}, %2;" : "=f"(lo), "=f"(hi) : "l"(v));
}

// ---------------------------------------------------------------------------
// Kernel 1: 3x3 SAME conv (64 -> 8) + exact GELU.
// Tile 64(w) x 16(h), 256 threads, 2 blocks/SM for latency hiding.
// Thread: 4 px x 8 oc (4 f32x2 oc-pairs).
// ---------------------------------------------------------------------------
#define TROWS 18          // 16 + 2 halo

__global__ void __launch_bounds__(256, 2)
conv1_gelu_kernel(const float* __restrict__ x, const float* __restrict__ w1)
{
    __shared__ float wsm[CIN * 9 * SHC];       // 18 KB
    __shared__ float dsm[2][TROWS * 68];       // 2 x 4.9 KB

    const int tid   = threadIdx.x;
    const int b     = blockIdx.z;
    const int tileX = blockIdx.x * 64;
    const int tileY = blockIdx.y * 16;

    for (int i = tid; i < CIN * 9 * SHC; i += 256) {
        int oc  = i & 7;
        int tap = (i >> 3) % 9;
        int ic  = i / 72;
        wsm[i] = w1[(oc * CIN + ic) * 9 + tap];
    }

    const float* xb = x + (size_t)b * CIN * NPIX;

    auto load_tile = [&](int ic, int buf) {
        const float* src = xb + (size_t)ic * NPIX;
        for (int i = tid; i < TROWS * 66; i += 256) {
            int r    = i / 66;
            int ccol = i - r * 66;
            int gy   = tileY - 1 + r;
            int gx   = tileX - 1 + ccol;
            float* dp = &dsm[buf][r * 68 + ccol];
            if ((unsigned)gy < (unsigned)HH && (unsigned)gx < (unsigned)WW)
                cp_async4(dp, src + gy * WW + gx);
            else
                *dp = 0.f;
        }
    };

    load_tile(0, 0);
    asm volatile("cp.async.commit_group;\n");

    const int tx = (tid & 15) * 4;   // 16 threads cover 64 px
    const int ty = tid >> 4;         // 16 rows

    ull acc2[4][4];                  // [oc-pair][px]
    #pragma unroll
    for (int q = 0; q < 4; q++)
        #pragma unroll
        for (int p = 0; p < 4; p++) acc2[q][p] = 0ull;

    for (int ic = 0; ic < CIN; ic++) {
        __syncthreads();
        if (ic + 1 < CIN) {
            load_tile(ic + 1, (ic + 1) & 1);
            asm volatile("cp.async.commit_group;\n");
            asm volatile("cp.async.wait_group 1;\n");
        } else {
            asm volatile("cp.async.wait_group 0;\n");
        }
        __syncthreads();

        const float* dd = &dsm[ic & 1][ty * 68 + tx];
        float rw[3][6];
        #pragma unroll
        for (int q = 0; q < 6; q++) {
            rw[0][q] = dd[q];
            rw[1][q] = dd[68 + q];
            rw[2][q] = dd[136 + q];
        }
        const float* wp = &wsm[ic * 72];
        #pragma unroll
        for (int t = 0; t < 9; t++) {
            const int ky = t / 3, kx = t % 3;
            const ull* wq = reinterpret_cast<const ull*>(wp + t * 8);
            ull w0 = wq[0], w1q = wq[1], w2q = wq[2], w3q = wq[3];
            #pragma unroll
            for (int p = 0; p < 4; p++) {
                ull d = dup2(rw[ky][p + kx]);
                acc2[0][p] = ffma2(d, w0,  acc2[0][p]);
                acc2[1][p] = ffma2(d, w1q, acc2[1][p]);
                acc2[2][p] = ffma2(d, w2q, acc2[2][p]);
                acc2[3][p] = ffma2(d, w3q, acc2[3][p]);
            }
        }
    }

    const int gy  = tileY + ty;
    const int gx0 = tileX + tx;
    const float inv_sqrt2 = 0.70710678118654752f;
    float* hbase = g_h + ((size_t)b * NPIX + (size_t)gy * WW + gx0) * SHC;
    #pragma unroll
    for (int p = 0; p < 4; p++) {
        float v[8];
        unpack2(acc2[0][p], v[0], v[1]);
        unpack2(acc2[1][p], v[2], v[3]);
        unpack2(acc2[2][p], v[4], v[5]);
        unpack2(acc2[3][p], v[6], v[7]);
        float4 o0, o1;
        float u;
        u = v[0]; o0.x = 0.5f * u * (1.f + erff(u * inv_sqrt2));
        u = v[1]; o0.y = 0.5f * u * (1.f + erff(u * inv_sqrt2));
        u = v[2]; o0.z = 0.5f * u * (1.f + erff(u * inv_sqrt2));
        u = v[3]; o0.w = 0.5f * u * (1.f + erff(u * inv_sqrt2));
        u = v[4]; o1.x = 0.5f * u * (1.f + erff(u * inv_sqrt2));
        u = v[5]; o1.y = 0.5f * u * (1.f + erff(u * inv_sqrt2));
        u = v[6]; o1.z = 0.5f * u * (1.f + erff(u * inv_sqrt2));
        u = v[7]; o1.w = 0.5f * u * (1.f + erff(u * inv_sqrt2));
        float4* hp = reinterpret_cast<float4*>(hbase + (size_t)p * SHC);
        hp[0] = o0;
        hp[1] = o1;
    }
}

// ---------------------------------------------------------------------------
// Kernel 2: EXACT R5 fuse (best measured: 133.5us). fp32 image in smem,
// 576 threads, 2-px ILP, constant-folded pixel-space coordinates.
// ---------------------------------------------------------------------------
#define PAD 200

__global__ void __launch_bounds__(576, 1)
fuse_kernel(const float* __restrict__ x, const float* __restrict__ w2,
            const float* __restrict__ b2, const float* __restrict__ lsc,
            float* __restrict__ out)
{
    extern __shared__ float img[];           // NPIX + PAD floats
    const int bc   = blockIdx.x >> 1;
    const int half = blockIdx.x & 1;
    const int c    = bc & 63;

    const float4* src  = reinterpret_cast<const float4*>(x + (size_t)bc * NPIX);
    float4*       dst4 = reinterpret_cast<float4*>(img);
    #pragma unroll 4
    for (int i = threadIdx.x; i < NPIX / 4; i += 576) dst4[i] = src[i];
    if (threadIdx.x < PAD / 4)
        reinterpret_cast<float4*>(img + NPIX)[threadIdx.x] = make_float4(0.f, 0.f, 0.f, 0.f);

    const float PXS = 9.55f;                 // 0.1 * 95.5
    ull w01[8], w23[8];
    #pragma unroll
    for (int s = 0; s < 8; s++) {
        w01[s] = pack2(__ldg(&w2[(4 * c + 0) * 8 + s]),
                       __ldg(&w2[(4 * c + 1) * 8 + s]) * PXS);
        w23[s] = pack2(__ldg(&w2[(4 * c + 2) * 8 + s]) * PXS,
                       __ldg(&w2[(4 * c + 3) * 8 + s]));
    }
    const ull bias01 = pack2(__ldg(&b2[4 * c + 0]), __ldg(&b2[4 * c + 1]) * PXS);
    const ull bias23 = pack2(__ldg(&b2[4 * c + 2]) * PXS, __ldg(&b2[4 * c + 3]));

    const float esc   = expf(__ldg(lsc));
    const float esc4  = 0.25f * esc;
    const float esc01 = 0.1f  * esc;
    const float* hb = g_h + (size_t)(bc >> 6) * NPIX * SHC;
    float* ob = out + (size_t)bc * NPIX;

    const float step = 2.0f / 191.0f;

    const int rphase = threadIdx.x / 192;            // 0..2
    const int xi     = threadIdx.x - rphase * 192;   // 0..191
    const float gxpix = (fmaf((float)xi, step, -1.0f) + 1.0f) * 95.5f;
    const int y0     = half * 96 + rphase;

    const int idxA0 = y0 * WW + xi;
    float4 ph0A = reinterpret_cast<const float4*>(hb + (size_t)idxA0 * SHC)[0];
    float4 ph1A = reinterpret_cast<const float4*>(hb + (size_t)idxA0 * SHC)[1];
    float4 ph0B = reinterpret_cast<const float4*>(hb + (size_t)(idxA0 + 48 * WW) * SHC)[0];
    float4 ph1B = reinterpret_cast<const float4*>(hb + (size_t)(idxA0 + 48 * WW) * SHC)[1];

    __syncthreads();

    #pragma unroll 1
    for (int k = 0; k < 16; k++) {
        const int yiA  = y0 + 3 * k;
        const int idxA = yiA * WW + xi;

        int   idx[2]   = { idxA, idxA + 48 * WW };
        float gypix[2] = { (fmaf((float)yiA,        step, -1.0f) + 1.0f) * 95.5f,
                           (fmaf((float)(yiA + 48), step, -1.0f) + 1.0f) * 95.5f };

        float4 h0[2], h1[2];
        h0[0] = ph0A; h1[0] = ph1A;
        h0[1] = ph0B; h1[1] = ph1B;
        if (k < 15) {
            const int nIdx = idxA + 3 * WW;
            ph0A = reinterpret_cast<const float4*>(hb + (size_t)nIdx * SHC)[0];
            ph1A = reinterpret_cast<const float4*>(hb + (size_t)nIdx * SHC)[1];
            ph0B = reinterpret_cast<const float4*>(hb + (size_t)(nIdx + 48 * WW) * SHC)[0];
            ph1B = reinterpret_cast<const float4*>(hb + (size_t)(nIdx + 48 * WW) * SHC)[1];
        }

        float s95[2], dxp[2], dyp[2], cvv[2];
        #pragma unroll
        for (int j = 0; j < 2; j++) {
            ull a01 = bias01, a23 = bias23;
            ull d;
            d = dup2(h0[j].x); a01 = ffma2(d, w01[0], a01); a23 = ffma2(d, w23[0], a23);
            d = dup2(h0[j].y); a01 = ffma2(d, w01[1], a01); a23 = ffma2(d, w23[1], a23);
            d = dup2(h0[j].z); a01 = ffma2(d, w01[2], a01); a23 = ffma2(d, w23[2], a23);
            d = dup2(h0[j].w); a01 = ffma2(d, w01[3], a01); a23 = ffma2(d, w23[3], a23);
            d = dup2(h1[j].x); a01 = ffma2(d, w01[4], a01); a23 = ffma2(d, w23[4], a23);
            d = dup2(h1[j].y); a01 = ffma2(d, w01[5], a01); a23 = ffma2(d, w23[5], a23);
            d = dup2(h1[j].z); a01 = ffma2(d, w01[6], a01); a23 = ffma2(d, w23[6], a23);
            d = dup2(h1[j].w); a01 = ffma2(d, w01[7], a01); a23 = ffma2(d, w23[7], a23);
            float a, bxp, byp, cv;
            unpack2(a01, a, bxp);
            unpack2(a23, byp, cv);

            float t  = __expf(-fabsf(a));
            float sp = fmaxf(a, 0.f) + __logf(1.0f + t);
            s95[j] = fsqrt_approx(fmaf(sp, 912.025f, 9.12025e-5f));
            dxp[j] = bxp;
            dyp[j] = byp;
            cvv[j] = fminf(fmaxf(cv, -5.f), 5.f);
        }

        #pragma unroll
        for (int j = 0; j < 2; j++) {
            float px3  = gxpix    + dxp[j];
            float px1  = px3      + s95[j];
            float px2  = px3      - s95[j];
            float py12 = gypix[j] + dyp[j];
            float py3  = py12     + s95[j];
            float py4  = py12     - s95[j];

            float pyc = fminf(fmaxf(py12, 0.f), 191.f);
            float y0f = floorf(pyc);
            float wy  = pyc - y0f;

            float pxc1 = fminf(fmaxf(px1, 0.f), 191.f);
            float x0f1 = floorf(pxc1);
            float wx1  = pxc1 - x0f1;
            int   o1   = (int)fmaf(y0f, 192.f, x0f1);
            float v00 = img[o1],       v01 = img[o1 + 1];
            float v10 = img[o1 + 192], v11 = img[o1 + 193];
            float top = fmaf(v01 - v00, wx1, v00);
            float bot = fmaf(v11 - v10, wx1, v10);
            float u1  = fmaf(bot - top, wy, top);

            float pxc2 = fminf(fmaxf(px2, 0.f), 191.f);
            float x0f2 = floorf(pxc2);
            float wx2  = pxc2 - x0f2;
            int   o2   = (int)fmaf(y0f, 192.f, x0f2);
            v00 = img[o2];       v01 = img[o2 + 1];
            v10 = img[o2 + 192]; v11 = img[o2 + 193];
            top = fmaf(v01 - v00, wx2, v00);
            bot = fmaf(v11 - v10, wx2, v10);
            float u2 = fmaf(bot - top, wy, top);

            float pxc3 = fminf(fmaxf(px3, 0.f), 191.f);
            float x0f3 = floorf(pxc3);
            float wx3  = pxc3 - x0f3;

            float pyc3 = fminf(fmaxf(py3, 0.f), 191.f);
            float y0f3 = floorf(pyc3);
            float wy3  = pyc3 - y0f3;
            int   o3   = (int)fmaf(y0f3, 192.f, x0f3);
            v00 = img[o3];       v01 = img[o3 + 1];
            v10 = img[o3 + 192]; v11 = img[o3 + 193];
            top = fmaf(v01 - v00, wx3, v00);
            bot = fmaf(v11 - v10, wx3, v10);
            float u3 = fmaf(bot - top, wy3, top);

            float pyc4 = fminf(fmaxf(py4, 0.f), 191.f);
            float y0f4 = floorf(pyc4);
            float wy4  = pyc4 - y0f4;
            int   o4   = (int)fmaf(y0f4, 192.f, x0f3);
            v00 = img[o4];       v01 = img[o4 + 1];
            v10 = img[o4 + 192]; v11 = img[o4 + 193];
            top = fmaf(v01 - v00, wx3, v00);
            bot = fmaf(v11 - v10, wx3, v10);
            float u4 = fmaf(bot - top, wy4, top);

            float usum = (u1 + u2) + (u3 + u4);
            float xv   = img[idx[j]];
            ob[idx[j]] = fmaf(esc4, usum, esc01 * cvv[j] * xv);
        }
    }
}

// ---------------------------------------------------------------------------
extern "C" void kernel_launch(void* const* d_in, const int* in_sizes, int n_in,
                              void* d_out, int out_size)
{
    const float *x = nullptr, *w1 = nullptr, *w2 = nullptr, *b2 = nullptr, *ls = nullptr;
    for (int i = 0; i < n_in; i++) {
        switch (in_sizes[i]) {
            case NB * CIN * NPIX: x  = (const float*)d_in[i]; break;
            case SHC * CIN * 9:   w1 = (const float*)d_in[i]; break;
            case 4 * CIN * SHC:   w2 = (const float*)d_in[i]; break;
            case 4 * CIN:         b2 = (const float*)d_in[i]; break;
            case 1:               ls = (const float*)d_in[i]; break;
            default: break;
        }
    }

    dim3 g1(3, 12, NB);                      // 64x16 tiles, ~2 blocks/SM
    conv1_gelu_kernel<<<g1, 256>>>(x, w1);

    const int smem = (NPIX + PAD) * (int)sizeof(float);
    cudaFuncSetAttribute(fuse_kernel, cudaFuncAttributeMaxDynamicSharedMemorySize, smem);
    fuse_kernel<<<NB * CIN * 2, 576, smem>>>(x, w2, b2, ls, (float*)d_out);
}

// round 8
// speedup vs baseline: 1.0883x; 1.0091x over previous
#include <cuda_runtime.h>
#include <math.h>

#define HH   192
#define WW   192
#define CIN  64
#define SHC  8
#define NB   8
#define NPIX (HH*WW)

typedef unsigned long long ull;

// scratch for h = gelu(conv1(x)), PIXEL-MAJOR: [b][pix][8 sh-channels] (9.4 MB)
__device__ float g_h[(size_t)NB * NPIX * SHC];

__device__ __forceinline__ void cp_async4(void* dst, const void* src) {
    unsigned s = (unsigned)__cvta_generic_to_shared(dst);
    asm volatile("cp.async.ca.shared.global [%0], [%1], 4;\n" :: "r"(s), "l"(src));
}
__device__ __forceinline__ float fsqrt_approx(float v) {
    float r; asm("sqrt.approx.f32 %0, %1;" : "=f"(r) : "f"(v)); return r;
}
// ---- f32x2 packed helpers ----
__device__ __forceinline__ ull ffma2(ull a, ull b, ull c) {
    ull r; asm("fma.rn.f32x2 %0, %1, %2, %3;" : "=l"(r) : "l"(a), "l"(b), "l"(c)); return r;
}
__device__ __forceinline__ ull dup2(float v) {
    ull r; asm("mov.b64 %0, {%1, %1};" : "=l"(r) : "f"(v)); return r;
}
__device__ __forceinline__ ull pack2(float lo, float hi) {
    ull r; asm("mov.b64 %0, {%1, %2};" : "=l"(r) : "f"(lo), "f"(hi)); return r;
}
__device__ __forceinline__ void unpack2(ull v, float& lo, float& hi) {
    asm("mov.b64 {%0, %1}, %2;" : "=f"(lo), "=f"(hi) : "l"(v));
}

// ---------------------------------------------------------------------------
// Kernel 1: 3x3 SAME conv (64 -> 8) + exact GELU.
// 512 threads, tile 64(w) x 32(h), 3-stage cp.async pipeline (distance 2),
// ONE syncthreads per ic. Thread: 4 px x 8 oc (4 f32x2 oc-pairs).
// Grid 144 blocks = exactly one wave; 4 warps/SMSP.
// ---------------------------------------------------------------------------
#define TROWS  34         // 32 + 2 halo
#define TSTRIDE 68
#define STAGES 3

__global__ void __launch_bounds__(512, 1)
conv1_gelu_kernel(const float* __restrict__ x, const float* __restrict__ w1)
{
    __shared__ float wsm[CIN * 9 * SHC];                 // 18 KB
    __shared__ float dsm[STAGES][TROWS * TSTRIDE];       // 3 x 9.2 KB

    const int tid   = threadIdx.x;
    const int b     = blockIdx.z;
    const int tileX = blockIdx.x * 64;
    const int tileY = blockIdx.y * 32;

    for (int i = tid; i < CIN * 9 * SHC; i += 512) {
        int oc  = i & 7;
        int tap = (i >> 3) % 9;
        int ic  = i / 72;
        wsm[i] = w1[(oc * CIN + ic) * 9 + tap];
    }

    const float* xb = x + (size_t)b * CIN * NPIX;

    auto load_tile = [&](int ic, int buf) {
        const float* src = xb + (size_t)ic * NPIX;
        for (int i = tid; i < TROWS * 66; i += 512) {
            int r    = i / 66;
            int ccol = i - r * 66;
            int gy   = tileY - 1 + r;
            int gx   = tileX - 1 + ccol;
            float* dp = &dsm[buf][r * TSTRIDE + ccol];
            if ((unsigned)gy < (unsigned)HH && (unsigned)gx < (unsigned)WW)
                cp_async4(dp, src + gy * WW + gx);
            else
                *dp = 0.f;
        }
    };

    // prime pipeline: stages 0,1 in flight
    load_tile(0, 0);
    asm volatile("cp.async.commit_group;\n");
    load_tile(1, 1);
    asm volatile("cp.async.commit_group;\n");

    const int tx = (tid & 15) * 4;   // 16 threads cover 64 px
    const int ty = tid >> 4;         // 32 rows

    ull acc2[4][4];                  // [oc-pair][px]
    #pragma unroll
    for (int q = 0; q < 4; q++)
        #pragma unroll
        for (int p = 0; p < 4; p++) acc2[q][p] = 0ull;

    for (int ic = 0; ic < CIN; ic++) {
        // stage ic arrived?
        if (ic < CIN - 2) asm volatile("cp.async.wait_group 1;\n");
        else              asm volatile("cp.async.wait_group 0;\n");
        // one barrier: publishes stage ic to all, and retires all reads of
        // the buffer that load(ic+2) will overwrite (read at iter ic-1).
        __syncthreads();
        if (ic + 2 < CIN) {
            load_tile(ic + 2, (ic + 2) % STAGES);
            asm volatile("cp.async.commit_group;\n");
        }

        const float* dd = &dsm[ic % STAGES][ty * TSTRIDE + tx];
        // hoisted broadcast duplicates (reused across the 3 kx shifts)
        ull rwd[3][6];
        #pragma unroll
        for (int q = 0; q < 6; q++) {
            rwd[0][q] = dup2(dd[q]);
            rwd[1][q] = dup2(dd[TSTRIDE + q]);
            rwd[2][q] = dup2(dd[2 * TSTRIDE + q]);
        }
        const float* wp = &wsm[ic * 72];
        #pragma unroll
        for (int t = 0; t < 9; t++) {
            const int ky = t / 3, kx = t % 3;
            const ull* wq = reinterpret_cast<const ull*>(wp + t * 8);
            ull w0 = wq[0], w1q = wq[1], w2q = wq[2], w3q = wq[3];
            #pragma unroll
            for (int p = 0; p < 4; p++) {
                ull d = rwd[ky][p + kx];
                acc2[0][p] = ffma2(d, w0,  acc2[0][p]);
                acc2[1][p] = ffma2(d, w1q, acc2[1][p]);
                acc2[2][p] = ffma2(d, w2q, acc2[2][p]);
                acc2[3][p] = ffma2(d, w3q, acc2[3][p]);
            }
        }
    }

    const int gy  = tileY + ty;
    const int gx0 = tileX + tx;
    const float inv_sqrt2 = 0.70710678118654752f;
    float* hbase = g_h + ((size_t)b * NPIX + (size_t)gy * WW + gx0) * SHC;
    #pragma unroll
    for (int p = 0; p < 4; p++) {
        float v[8];
        unpack2(acc2[0][p], v[0], v[1]);
        unpack2(acc2[1][p], v[2], v[3]);
        unpack2(acc2[2][p], v[4], v[5]);
        unpack2(acc2[3][p], v[6], v[7]);
        float4 o0, o1;
        float u;
        u = v[0]; o0.x = 0.5f * u * (1.f + erff(u * inv_sqrt2));
        u = v[1]; o0.y = 0.5f * u * (1.f + erff(u * inv_sqrt2));
        u = v[2]; o0.z = 0.5f * u * (1.f + erff(u * inv_sqrt2));
        u = v[3]; o0.w = 0.5f * u * (1.f + erff(u * inv_sqrt2));
        u = v[4]; o1.x = 0.5f * u * (1.f + erff(u * inv_sqrt2));
        u = v[5]; o1.y = 0.5f * u * (1.f + erff(u * inv_sqrt2));
        u = v[6]; o1.z = 0.5f * u * (1.f + erff(u * inv_sqrt2));
        u = v[7]; o1.w = 0.5f * u * (1.f + erff(u * inv_sqrt2));
        float4* hp = reinterpret_cast<float4*>(hbase + (size_t)p * SHC);
        hp[0] = o0;
        hp[1] = o1;
    }
}

// ---------------------------------------------------------------------------
// Kernel 2: EXACT R5 fuse (best measured: 133.5us).
// ---------------------------------------------------------------------------
#define PAD 200

__global__ void __launch_bounds__(576, 1)
fuse_kernel(const float* __restrict__ x, const float* __restrict__ w2,
            const float* __restrict__ b2, const float* __restrict__ lsc,
            float* __restrict__ out)
{
    extern __shared__ float img[];           // NPIX + PAD floats
    const int bc   = blockIdx.x >> 1;
    const int half = blockIdx.x & 1;
    const int c    = bc & 63;

    const float4* src  = reinterpret_cast<const float4*>(x + (size_t)bc * NPIX);
    float4*       dst4 = reinterpret_cast<float4*>(img);
    #pragma unroll 4
    for (int i = threadIdx.x; i < NPIX / 4; i += 576) dst4[i] = src[i];
    if (threadIdx.x < PAD / 4)
        reinterpret_cast<float4*>(img + NPIX)[threadIdx.x] = make_float4(0.f, 0.f, 0.f, 0.f);

    const float PXS = 9.55f;                 // 0.1 * 95.5
    ull w01[8], w23[8];
    #pragma unroll
    for (int s = 0; s < 8; s++) {
        w01[s] = pack2(__ldg(&w2[(4 * c + 0) * 8 + s]),
                       __ldg(&w2[(4 * c + 1) * 8 + s]) * PXS);
        w23[s] = pack2(__ldg(&w2[(4 * c + 2) * 8 + s]) * PXS,
                       __ldg(&w2[(4 * c + 3) * 8 + s]));
    }
    const ull bias01 = pack2(__ldg(&b2[4 * c + 0]), __ldg(&b2[4 * c + 1]) * PXS);
    const ull bias23 = pack2(__ldg(&b2[4 * c + 2]) * PXS, __ldg(&b2[4 * c + 3]));

    const float esc   = expf(__ldg(lsc));
    const float esc4  = 0.25f * esc;
    const float esc01 = 0.1f  * esc;
    const float* hb = g_h + (size_t)(bc >> 6) * NPIX * SHC;
    float* ob = out + (size_t)bc * NPIX;

    const float step = 2.0f / 191.0f;

    const int rphase = threadIdx.x / 192;            // 0..2
    const int xi     = threadIdx.x - rphase * 192;   // 0..191
    const float gxpix = (fmaf((float)xi, step, -1.0f) + 1.0f) * 95.5f;
    const int y0     = half * 96 + rphase;

    const int idxA0 = y0 * WW + xi;
    float4 ph0A = reinterpret_cast<const float4*>(hb + (size_t)idxA0 * SHC)[0];
    float4 ph1A = reinterpret_cast<const float4*>(hb + (size_t)idxA0 * SHC)[1];
    float4 ph0B = reinterpret_cast<const float4*>(hb + (size_t)(idxA0 + 48 * WW) * SHC)[0];
    float4 ph1B = reinterpret_cast<const float4*>(hb + (size_t)(idxA0 + 48 * WW) * SHC)[1];

    __syncthreads();

    #pragma unroll 1
    for (int k = 0; k < 16; k++) {
        const int yiA  = y0 + 3 * k;
        const int idxA = yiA * WW + xi;

        int   idx[2]   = { idxA, idxA + 48 * WW };
        float gypix[2] = { (fmaf((float)yiA,        step, -1.0f) + 1.0f) * 95.5f,
                           (fmaf((float)(yiA + 48), step, -1.0f) + 1.0f) * 95.5f };

        float4 h0[2], h1[2];
        h0[0] = ph0A; h1[0] = ph1A;
        h0[1] = ph0B; h1[1] = ph1B;
        if (k < 15) {
            const int nIdx = idxA + 3 * WW;
            ph0A = reinterpret_cast<const float4*>(hb + (size_t)nIdx * SHC)[0];
            ph1A = reinterpret_cast<const float4*>(hb + (size_t)nIdx * SHC)[1];
            ph0B = reinterpret_cast<const float4*>(hb + (size_t)(nIdx + 48 * WW) * SHC)[0];
            ph1B = reinterpret_cast<const float4*>(hb + (size_t)(nIdx + 48 * WW) * SHC)[1];
        }

        float s95[2], dxp[2], dyp[2], cvv[2];
        #pragma unroll
        for (int j = 0; j < 2; j++) {
            ull a01 = bias01, a23 = bias23;
            ull d;
            d = dup2(h0[j].x); a01 = ffma2(d, w01[0], a01); a23 = ffma2(d, w23[0], a23);
            d = dup2(h0[j].y); a01 = ffma2(d, w01[1], a01); a23 = ffma2(d, w23[1], a23);
            d = dup2(h0[j].z); a01 = ffma2(d, w01[2], a01); a23 = ffma2(d, w23[2], a23);
            d = dup2(h0[j].w); a01 = ffma2(d, w01[3], a01); a23 = ffma2(d, w23[3], a23);
            d = dup2(h1[j].x); a01 = ffma2(d, w01[4], a01); a23 = ffma2(d, w23[4], a23);
            d = dup2(h1[j].y); a01 = ffma2(d, w01[5], a01); a23 = ffma2(d, w23[5], a23);
            d = dup2(h1[j].z); a01 = ffma2(d, w01[6], a01); a23 = ffma2(d, w23[6], a23);
            d = dup2(h1[j].w); a01 = ffma2(d, w01[7], a01); a23 = ffma2(d, w23[7], a23);
            float a, bxp, byp, cv;
            unpack2(a01, a, bxp);
            unpack2(a23, byp, cv);

            float t  = __expf(-fabsf(a));
            float sp = fmaxf(a, 0.f) + __logf(1.0f + t);
            s95[j] = fsqrt_approx(fmaf(sp, 912.025f, 9.12025e-5f));
            dxp[j] = bxp;
            dyp[j] = byp;
            cvv[j] = fminf(fmaxf(cv, -5.f), 5.f);
        }

        #pragma unroll
        for (int j = 0; j < 2; j++) {
            float px3  = gxpix    + dxp[j];
            float px1  = px3      + s95[j];
            float px2  = px3      - s95[j];
            float py12 = gypix[j] + dyp[j];
            float py3  = py12     + s95[j];
            float py4  = py12     - s95[j];

            float pyc = fminf(fmaxf(py12, 0.f), 191.f);
            float y0f = floorf(pyc);
            float wy  = pyc - y0f;

            float pxc1 = fminf(fmaxf(px1, 0.f), 191.f);
            float x0f1 = floorf(pxc1);
            float wx1  = pxc1 - x0f1;
            int   o1   = (int)fmaf(y0f, 192.f, x0f1);
            float v00 = img[o1],       v01 = img[o1 + 1];
            float v10 = img[o1 + 192], v11 = img[o1 + 193];
            float top = fmaf(v01 - v00, wx1, v00);
            float bot = fmaf(v11 - v10, wx1, v10);
            float u1  = fmaf(bot - top, wy, top);

            float pxc2 = fminf(fmaxf(px2, 0.f), 191.f);
            float x0f2 = floorf(pxc2);
            float wx2  = pxc2 - x0f2;
            int   o2   = (int)fmaf(y0f, 192.f, x0f2);
            v00 = img[o2];       v01 = img[o2 + 1];
            v10 = img[o2 + 192]; v11 = img[o2 + 193];
            top = fmaf(v01 - v00, wx2, v00);
            bot = fmaf(v11 - v10, wx2, v10);
            float u2 = fmaf(bot - top, wy, top);

            float pxc3 = fminf(fmaxf(px3, 0.f), 191.f);
            float x0f3 = floorf(pxc3);
            float wx3  = pxc3 - x0f3;

            float pyc3 = fminf(fmaxf(py3, 0.f), 191.f);
            float y0f3 = floorf(pyc3);
            float wy3  = pyc3 - y0f3;
            int   o3   = (int)fmaf(y0f3, 192.f, x0f3);
            v00 = img[o3];       v01 = img[o3 + 1];
            v10 = img[o3 + 192]; v11 = img[o3 + 193];
            top = fmaf(v01 - v00, wx3, v00);
            bot = fmaf(v11 - v10, wx3, v10);
            float u3 = fmaf(bot - top, wy3, top);

            float pyc4 = fminf(fmaxf(py4, 0.f), 191.f);
            float y0f4 = floorf(pyc4);
            float wy4  = pyc4 - y0f4;
            int   o4   = (int)fmaf(y0f4, 192.f, x0f3);
            v00 = img[o4];       v01 = img[o4 + 1];
            v10 = img[o4 + 192]; v11 = img[o4 + 193];
            top = fmaf(v01 - v00, wx3, v00);
            bot = fmaf(v11 - v10, wx3, v10);
            float u4 = fmaf(bot - top, wy4, top);

            float usum = (u1 + u2) + (u3 + u4);
            float xv   = img[idx[j]];
            ob[idx[j]] = fmaf(esc4, usum, esc01 * cvv[j] * xv);
        }
    }
}

// ---------------------------------------------------------------------------
extern "C" void kernel_launch(void* const* d_in, const int* in_sizes, int n_in,
                              void* d_out, int out_size)
{
    const float *x = nullptr, *w1 = nullptr, *w2 = nullptr, *b2 = nullptr, *ls = nullptr;
    for (int i = 0; i < n_in; i++) {
        switch (in_sizes[i]) {
            case NB * CIN * NPIX: x  = (const float*)d_in[i]; break;
            case SHC * CIN * 9:   w1 = (const float*)d_in[i]; break;
            case 4 * CIN * SHC:   w2 = (const float*)d_in[i]; break;
            case 4 * CIN:         b2 = (const float*)d_in[i]; break;
            case 1:               ls = (const float*)d_in[i]; break;
            default: break;
        }
    }

    dim3 g1(3, 6, NB);                       // 64x32 tiles, 144 blocks = 1 wave
    conv1_gelu_kernel<<<g1, 512>>>(x, w1);

    const int smem = (NPIX + PAD) * (int)sizeof(float);
    cudaFuncSetAttribute(fuse_kernel, cudaFuncAttributeMaxDynamicSharedMemorySize, smem);
    fuse_kernel<<<NB * CIN * 2, 576, smem>>>(x, w2, b2, ls, (float*)d_out);
}